// round 10
// baseline (speedup 1.0000x reference)
#include <cuda_runtime.h>
#include <cstdint>

#define N_NODES 100000
#define N_EDGES 1600000
#define HC 128            // HEADS * OUT_CH
#define HEADS 4
#define OUT_CH 32
#define EDGE_CH 32
#define SCAN_BLK 1024
#define SCAN_NB ((N_NODES + SCAN_BLK - 1) / SCAN_BLK)   // 98

__constant__ float c_neg_slope = 0.2f;

// ---------------- scratch (static device globals; no allocation) ----------------
__device__ float  g_xl[(size_t)N_NODES * HC];   // 51.2 MB projected node features
__device__ float  g_al[N_NODES * HEADS];        // alpha_l per node/head
__device__ float  g_ar[N_NODES * HEADS];        // alpha_r per node/head
__device__ float  g_we[HC];                     // folded We^T * att_e  [H][32]
__device__ float  g_ulr[8 * HC];                // folded Wl^T*att_l (rows 0-3) / att_r (4-7)
__device__ float4 g_denom[N_NODES];             // softmax denominators (sum of ex)
__device__ int    g_hist[N_NODES];              // in-degree histogram
__device__ int    g_offs[N_NODES];              // CSR start offsets (exclusive scan)
__device__ int    g_cursor[N_NODES];            // scatter cursors
__device__ int    g_bsum[SCAN_NB];              // scan block sums
__device__ int    g_csr_src[N_EDGES];           // dst-sorted source node ids
__device__ float4 g_csr_ex[N_EDGES];            // dst-sorted UNnormalized exp(logit)

// vectorized 16B global reduction (sm_90+)
__device__ __forceinline__ void red_add_v4(float4* p, float4 v) {
    asm volatile("red.global.add.v4.f32 [%0], {%1, %2, %3, %4};"
                 :: "l"(p), "f"(v.x), "f"(v.y), "f"(v.z), "f"(v.w)
                 : "memory");
}

// ---------------- zero hist + denom ----------------
__global__ void k_zero() {
    int idx = blockIdx.x * blockDim.x + threadIdx.x;
    if (idx < N_NODES * HEADS) ((float*)g_denom)[idx] = 0.0f;
    if (idx < N_NODES) g_hist[idx] = 0;
}

// ---------------- fold We*att_e AND Wl*att_l / Wl*att_r (one block, 128 threads) ----------------
__global__ void k_fold(const float* __restrict__ Wl, const float* __restrict__ We,
                       const float* __restrict__ att_l, const float* __restrict__ att_r,
                       const float* __restrict__ att_e) {
    int t = threadIdx.x;            // 0..127
    {   // We fold: t = h*32 + k
        int h = t >> 5, k = t & 31;
        float s = 0.0f;
#pragma unroll
        for (int c = 0; c < OUT_CH; c++)
            s += We[(h * OUT_CH + c) * EDGE_CH + k] * att_e[h * OUT_CH + c];
        g_we[t] = s;
    }
    {   // Wl folds: t = input channel k
#pragma unroll
        for (int h = 0; h < HEADS; h++) {
            float sl = 0.0f, sr = 0.0f;
#pragma unroll
            for (int c = 0; c < OUT_CH; c++) {
                float w = Wl[(size_t)(h * OUT_CH + c) * HC + t];
                sl += w * att_l[h * OUT_CH + c];
                sr += w * att_r[h * OUT_CH + c];
            }
            g_ulr[h * HC + t]           = sl;
            g_ulr[(HEADS + h) * HC + t] = sr;
        }
    }
}

// ---------------- alpha_l / alpha_r directly from x (no xl dependency) ----------------
// 8 lanes per node; lane handles float4s {sub + 8*i}; shfl-reduce across 8 lanes.  (R6-validated)
__global__ void k_alphas(const float* __restrict__ x) {
    __shared__ float us[8 * HC];
    for (int i = threadIdx.x; i < 8 * HC; i += blockDim.x) us[i] = g_ulr[i];
    __syncthreads();

    int sub  = threadIdx.x & 7;
    int node = blockIdx.x * (blockDim.x >> 3) + (threadIdx.x >> 3);
    if (node >= N_NODES) return;

    const float4* __restrict__ row = (const float4*)(x + (size_t)node * HC);
    float p[8];
#pragma unroll
    for (int j = 0; j < 8; j++) p[j] = 0.f;
#pragma unroll
    for (int i = 0; i < 4; i++) {
        int c4 = sub + 8 * i;
        float4 xv = row[c4];
#pragma unroll
        for (int j = 0; j < 8; j++) {
            float4 uv = ((const float4*)us)[j * 32 + c4];
            p[j] += xv.x * uv.x + xv.y * uv.y + xv.z * uv.z + xv.w * uv.w;
        }
    }
#pragma unroll
    for (int off = 4; off; off >>= 1)
#pragma unroll
        for (int j = 0; j < 8; j++)
            p[j] += __shfl_down_sync(0xffffffffu, p[j], off, 8);
    if (sub == 0) {
        ((float4*)g_al)[node] = make_float4(p[0], p[1], p[2], p[3]);
        ((float4*)g_ar)[node] = make_float4(p[4], p[5], p[6], p[7]);
    }
}

// ---------------- in-degree histogram (dst only, int4 vectorized) ----------------
__global__ void k_hist(const int* __restrict__ ei) {
    int i = blockIdx.x * blockDim.x + threadIdx.x;   // quad index
    if (i * 4 >= N_EDGES) return;
    int4 d = ((const int4*)(ei + N_EDGES))[i];
    atomicAdd(&g_hist[d.x], 1);
    atomicAdd(&g_hist[d.y], 1);
    atomicAdd(&g_hist[d.z], 1);
    atomicAdd(&g_hist[d.w], 1);
}

// ---------------- xl = x @ Wl^T (8-node tiles; alpha epilogue removed) ----------------
__global__ void k_gemm(const float* __restrict__ x, const float* __restrict__ Wl) {
    __shared__ float xs[8][HC];
    const int j = threadIdx.x;          // 0..127 output column
    const float4* __restrict__ Wrow = (const float4*)(Wl + (size_t)j * HC); // 32 float4

    for (int base = blockIdx.x * 8; base < N_NODES; base += gridDim.x * 8) {
        __syncthreads();
        {
            const float4* src = (const float4*)(x + (size_t)base * HC);
            ((float4*)xs)[j]       = src[j];
            ((float4*)xs)[j + 128] = src[j + 128];
        }
        __syncthreads();

        float acc[8];
#pragma unroll
        for (int i = 0; i < 8; i++) acc[i] = 0.f;
#pragma unroll 4
        for (int k4 = 0; k4 < HC / 4; k4++) {
            float4 wv = Wrow[k4];
#pragma unroll
            for (int i = 0; i < 8; i++) {
                float4 xv = ((const float4*)xs[i])[k4];
                acc[i] += wv.x * xv.x + wv.y * xv.y + wv.z * xv.z + wv.w * xv.w;
            }
        }
#pragma unroll
        for (int i = 0; i < 8; i++)
            g_xl[(size_t)(base + i) * HC + j] = acc[i];
    }
}

// ---------------- scan kernels: exclusive prefix over g_hist -> g_offs ----------------
__global__ void k_scan1() {
    __shared__ int wsum[32];
    int i = blockIdx.x * SCAN_BLK + threadIdx.x;
    int lane = threadIdx.x & 31, wid = threadIdx.x >> 5;
    int v = (i < N_NODES) ? g_hist[i] : 0;
    int inc = v;
#pragma unroll
    for (int off = 1; off < 32; off <<= 1) {
        int t = __shfl_up_sync(0xffffffffu, inc, off);
        if (lane >= off) inc += t;
    }
    if (lane == 31) wsum[wid] = inc;
    __syncthreads();
    if (wid == 0) {
        int s = wsum[lane];
#pragma unroll
        for (int off = 1; off < 32; off <<= 1) {
            int t = __shfl_up_sync(0xffffffffu, s, off);
            if (lane >= off) s += t;
        }
        wsum[lane] = s;
    }
    __syncthreads();
    int base = (wid > 0) ? wsum[wid - 1] : 0;
    if (i < N_NODES) g_offs[i] = base + inc - v;
    if (threadIdx.x == SCAN_BLK - 1) g_bsum[blockIdx.x] = base + inc;
}

__global__ void k_scan2() {   // single block, scan SCAN_NB (=98) block totals, exclusive
    __shared__ int wsum[4];
    int lane = threadIdx.x & 31, wid = threadIdx.x >> 5;
    int v = (threadIdx.x < SCAN_NB) ? g_bsum[threadIdx.x] : 0;
    int inc = v;
#pragma unroll
    for (int off = 1; off < 32; off <<= 1) {
        int t = __shfl_up_sync(0xffffffffu, inc, off);
        if (lane >= off) inc += t;
    }
    if (lane == 31) wsum[wid] = inc;
    __syncthreads();
    int base = 0;
    for (int w = 0; w < wid; w++) base += wsum[w];
    if (threadIdx.x < SCAN_NB) g_bsum[threadIdx.x] = base + inc - v;
}

__global__ void k_scan3() {   // apply block offsets; init cursor = offs
    int i = blockIdx.x * SCAN_BLK + threadIdx.x;
    if (i < N_NODES) {
        int o = g_offs[i] + g_bsum[blockIdx.x];
        g_offs[i]   = o;
        g_cursor[i] = o;
    }
}

// ---------------- fused: logits + leaky-relu + exp + denom + CSR scatter (R4 body) ----------------
__global__ void k_logits(const float* __restrict__ edge_attr, const int* __restrict__ ei) {
    __shared__ float we_s[HC];
    if (threadIdx.x < HC) we_s[threadIdx.x] = g_we[threadIdx.x];
    __syncthreads();

    int e = blockIdx.x * blockDim.x + threadIdx.x;
    if (e >= N_EDGES) return;

    const float4* __restrict__ row = (const float4*)(edge_attr + (size_t)e * EDGE_CH);
    const float4* w0 = (const float4*)(we_s);
    const float4* w1 = (const float4*)(we_s + 32);
    const float4* w2 = (const float4*)(we_s + 64);
    const float4* w3 = (const float4*)(we_s + 96);
    float p0 = 0.f, p1 = 0.f, p2 = 0.f, p3 = 0.f;
#pragma unroll
    for (int i = 0; i < 8; i++) {
        float4 v = row[i];
        float4 a0 = w0[i], a1 = w1[i], a2 = w2[i], a3 = w3[i];
        p0 += v.x * a0.x + v.y * a0.y + v.z * a0.z + v.w * a0.w;
        p1 += v.x * a1.x + v.y * a1.y + v.z * a1.z + v.w * a1.w;
        p2 += v.x * a2.x + v.y * a2.y + v.z * a2.z + v.w * a2.w;
        p3 += v.x * a3.x + v.y * a3.y + v.z * a3.z + v.w * a3.w;
    }
    int src = ei[e];
    int dst = ei[N_EDGES + e];
    float4 al = ((const float4*)g_al)[src];
    float4 ar = ((const float4*)g_ar)[dst];
    float a0 = al.x + ar.x + p0;
    float a1 = al.y + ar.y + p1;
    float a2 = al.z + ar.z + p2;
    float a3 = al.w + ar.w + p3;
    a0 = (a0 > 0.f) ? a0 : c_neg_slope * a0;
    a1 = (a1 > 0.f) ? a1 : c_neg_slope * a1;
    a2 = (a2 > 0.f) ? a2 : c_neg_slope * a2;
    a3 = (a3 > 0.f) ? a3 : c_neg_slope * a3;
    float4 ex = make_float4(__expf(a0), __expf(a1), __expf(a2), __expf(a3));
    int pos = atomicAdd(&g_cursor[dst], 1);
    g_csr_src[pos] = src;
    g_csr_ex[pos]  = ex;
    red_add_v4(&g_denom[dst], ex);
}

// ---------------- gather aggregation: one warp per dst node (R4 body) ----------------
__global__ void k_agg(const float* __restrict__ bias, float* __restrict__ out) {
    const int lane = threadIdx.x & 31;
    const int h    = lane >> 3;                 // head owning this lane's float4
    int node = blockIdx.x * (blockDim.x >> 5) + (threadIdx.x >> 5);
    if (node >= N_NODES) return;

    int beg = g_offs[node];
    int end = g_cursor[node];                   // start + degree
    float4 acc = make_float4(0.f, 0.f, 0.f, 0.f);

    int pos = beg;
    for (; pos + 3 < end; pos += 4) {
        int s0 = g_csr_src[pos];
        int s1 = g_csr_src[pos + 1];
        int s2 = g_csr_src[pos + 2];
        int s3 = g_csr_src[pos + 3];
        float a0 = ((const float*)g_csr_ex)[(size_t)pos * 4 + h];
        float a1 = ((const float*)g_csr_ex)[(size_t)(pos + 1) * 4 + h];
        float a2 = ((const float*)g_csr_ex)[(size_t)(pos + 2) * 4 + h];
        float a3 = ((const float*)g_csr_ex)[(size_t)(pos + 3) * 4 + h];
        float4 v0 = ((const float4*)g_xl)[(size_t)s0 * 32 + lane];
        float4 v1 = ((const float4*)g_xl)[(size_t)s1 * 32 + lane];
        float4 v2 = ((const float4*)g_xl)[(size_t)s2 * 32 + lane];
        float4 v3 = ((const float4*)g_xl)[(size_t)s3 * 32 + lane];
        acc.x += a0 * v0.x + a1 * v1.x + a2 * v2.x + a3 * v3.x;
        acc.y += a0 * v0.y + a1 * v1.y + a2 * v2.y + a3 * v3.y;
        acc.z += a0 * v0.z + a1 * v1.z + a2 * v2.z + a3 * v3.z;
        acc.w += a0 * v0.w + a1 * v1.w + a2 * v2.w + a3 * v3.w;
    }
    for (; pos < end; pos++) {
        int s0 = g_csr_src[pos];
        float a0 = ((const float*)g_csr_ex)[(size_t)pos * 4 + h];
        float4 v0 = ((const float4*)g_xl)[(size_t)s0 * 32 + lane];
        acc.x += a0 * v0.x; acc.y += a0 * v0.y; acc.z += a0 * v0.z; acc.w += a0 * v0.w;
    }
    float inv = 1.0f / (((const float*)g_denom)[(size_t)node * 4 + h] + 1e-16f);
    float4 b = ((const float4*)bias)[lane];
    acc.x = acc.x * inv + b.x;
    acc.y = acc.y * inv + b.y;
    acc.z = acc.z * inv + b.z;
    acc.w = acc.w * inv + b.w;
    ((float4*)out)[(size_t)node * 32 + lane] = acc;
}

// ---------------- launch: gemm decoupled from logits -> they run concurrently ----------------
extern "C" void kernel_launch(void* const* d_in, const int* in_sizes, int n_in,
                              void* d_out, int out_size) {
    const float* x         = (const float*)d_in[0];
    const float* edge_attr = (const float*)d_in[1];
    const float* Wl        = (const float*)d_in[2];
    const float* We        = (const float*)d_in[3];
    const float* att_l     = (const float*)d_in[4];
    const float* att_r     = (const float*)d_in[5];
    const float* att_e     = (const float*)d_in[6];
    const float* bias      = (const float*)d_in[7];
    const int*   ei        = (const int*)d_in[8];
    float* out = (float*)d_out;

    cudaStream_t sA, sB;
    cudaStreamCreateWithFlags(&sA, cudaStreamNonBlocking);
    cudaStreamCreateWithFlags(&sB, cudaStreamNonBlocking);
    cudaEvent_t evRoot, evA, evB;
    cudaEventCreateWithFlags(&evRoot, cudaEventDisableTiming);
    cudaEventCreateWithFlags(&evA,    cudaEventDisableTiming);
    cudaEventCreateWithFlags(&evB,    cudaEventDisableTiming);

    cudaEventRecord(evRoot, 0);
    cudaStreamWaitEvent(sA, evRoot, 0);
    cudaStreamWaitEvent(sB, evRoot, 0);

    // Branch A (sA): edge-prep chain — zero, hist, scans (depends only on ei)
    k_zero <<<(N_NODES * HEADS + 255) / 256, 256, 0, sA>>>();
    k_hist <<<(N_EDGES / 4 + 255) / 256, 256, 0, sA>>>(ei);
    k_scan1<<<SCAN_NB, SCAN_BLK, 0, sA>>>();
    k_scan2<<<1, 128, 0, sA>>>();
    k_scan3<<<SCAN_NB, SCAN_BLK, 0, sA>>>();
    cudaEventRecord(evA, sA);

    // Branch B (sB): xl GEMM — independent of logits now; overlaps it
    k_gemm<<<2368, 128, 0, sB>>>(x, Wl);
    cudaEventRecord(evB, sB);

    // Main: folds -> alphas -> (wait scans) -> logits, concurrent with gemm on sB
    k_fold<<<1, 128>>>(Wl, We, att_l, att_r, att_e);
    k_alphas<<<(N_NODES * 8 + 255) / 256, 256>>>(x);
    cudaStreamWaitEvent(0, evA, 0);
    k_logits<<<(N_EDGES + 255) / 256, 256>>>(edge_attr, ei);

    // join gemm, then aggregate (xl freshly L2-warm)
    cudaStreamWaitEvent(0, evB, 0);
    k_agg<<<(N_NODES * 32 + 255) / 256, 256>>>(bias, out);

    cudaEventDestroy(evRoot);
    cudaEventDestroy(evA);
    cudaEventDestroy(evB);
    cudaStreamDestroy(sA);
    cudaStreamDestroy(sB);
}

// round 11
// speedup vs baseline: 1.0275x; 1.0275x over previous
#include <cuda_runtime.h>
#include <cstdint>

#define N_NODES 100000
#define N_EDGES 1600000
#define HC 128            // HEADS * OUT_CH
#define HEADS 4
#define OUT_CH 32
#define EDGE_CH 32
#define SCAN_BLK 1024
#define SCAN_NB ((N_NODES + SCAN_BLK - 1) / SCAN_BLK)   // 98

__constant__ float c_neg_slope = 0.2f;

// ---------------- scratch (static device globals; no allocation) ----------------
__device__ float  g_xl[(size_t)N_NODES * HC];   // 51.2 MB projected node features
__device__ float  g_al[N_NODES * HEADS];        // alpha_l per node/head
__device__ float  g_ar[N_NODES * HEADS];        // alpha_r per node/head
__device__ float  g_we[HC];                     // folded We^T * att_e  [H][32]
__device__ float4 g_denom[N_NODES];             // softmax denominators (sum of ex)
__device__ int    g_hist[N_NODES];              // in-degree histogram
__device__ int    g_offs[N_NODES];              // CSR start offsets (exclusive scan)
__device__ int    g_cursor[N_NODES];            // scatter cursors
__device__ int    g_bsum[SCAN_NB];              // scan block sums
__device__ int    g_csr_src[N_EDGES];           // dst-sorted source node ids
__device__ float4 g_csr_ex[N_EDGES];            // dst-sorted UNnormalized exp(logit)

// vectorized 16B global reduction (sm_90+)
__device__ __forceinline__ void red_add_v4(float4* p, float4 v) {
    asm volatile("red.global.add.v4.f32 [%0], {%1, %2, %3, %4};"
                 :: "l"(p), "f"(v.x), "f"(v.y), "f"(v.z), "f"(v.w)
                 : "memory");
}

// ---------------- zero hist + denom ----------------
__global__ void k_zero() {
    int idx = blockIdx.x * blockDim.x + threadIdx.x;
    if (idx < N_NODES * HEADS) ((float*)g_denom)[idx] = 0.0f;
    if (idx < N_NODES) g_hist[idx] = 0;
}

// ---------------- fold We with att_e  ->  g_we[h*32+k] ----------------
__global__ void k_wepre(const float* __restrict__ We, const float* __restrict__ att_e) {
    int t = threadIdx.x;           // 0..127  = h*32 + k
    int h = t >> 5, k = t & 31;
    float s = 0.0f;
#pragma unroll
    for (int c = 0; c < OUT_CH; c++)
        s += We[(h * OUT_CH + c) * EDGE_CH + k] * att_e[h * OUT_CH + c];
    g_we[t] = s;
}

// ---------------- in-degree histogram (dst only, int4 vectorized, streaming reads) ----------------
__global__ void k_hist(const int* __restrict__ ei) {
    int i = blockIdx.x * blockDim.x + threadIdx.x;   // quad index
    if (i * 4 >= N_EDGES) return;
    int4 d = __ldcs((const int4*)(ei + N_EDGES) + i);
    atomicAdd(&g_hist[d.x], 1);
    atomicAdd(&g_hist[d.y], 1);
    atomicAdd(&g_hist[d.z], 1);
    atomicAdd(&g_hist[d.w], 1);
}

// ---------------- xl = x @ Wl^T, plus alpha_l / alpha_r (8-node tiles) ----------------
// x is read-once -> streaming loads (keep L2 for the xl being produced)
__global__ void k_gemm(const float* __restrict__ x, const float* __restrict__ Wl,
                       const float* __restrict__ att_l, const float* __restrict__ att_r) {
    __shared__ float xs[8][HC];
    const int j    = threadIdx.x;       // 0..127 output column
    const int lane = j & 31;
    const int w    = j >> 5;            // head index
    const float al_w = att_l[j];
    const float ar_w = att_r[j];
    const float4* __restrict__ Wrow = (const float4*)(Wl + (size_t)j * HC); // 32 float4

    for (int base = blockIdx.x * 8; base < N_NODES; base += gridDim.x * 8) {
        __syncthreads();
        {
            const float4* src = (const float4*)(x + (size_t)base * HC);
            ((float4*)xs)[j]       = __ldcs(src + j);
            ((float4*)xs)[j + 128] = __ldcs(src + j + 128);
        }
        __syncthreads();

        float acc[8];
#pragma unroll
        for (int i = 0; i < 8; i++) acc[i] = 0.f;
#pragma unroll 4
        for (int k4 = 0; k4 < HC / 4; k4++) {
            float4 wv = Wrow[k4];
#pragma unroll
            for (int i = 0; i < 8; i++) {
                float4 xv = ((const float4*)xs[i])[k4];
                acc[i] += wv.x * xv.x + wv.y * xv.y + wv.z * xv.z + wv.w * xv.w;
            }
        }
#pragma unroll
        for (int i = 0; i < 8; i++) {
            g_xl[(size_t)(base + i) * HC + j] = acc[i];
            float pl = acc[i] * al_w;
            float pr = acc[i] * ar_w;
#pragma unroll
            for (int off = 16; off; off >>= 1) {
                pl += __shfl_xor_sync(0xffffffffu, pl, off);
                pr += __shfl_xor_sync(0xffffffffu, pr, off);
            }
            if (lane == 0) {
                g_al[(base + i) * HEADS + w] = pl;
                g_ar[(base + i) * HEADS + w] = pr;
            }
        }
    }
}

// ---------------- scan kernels: exclusive prefix over g_hist -> g_offs ----------------
__global__ void k_scan1() {
    __shared__ int wsum[32];
    int i = blockIdx.x * SCAN_BLK + threadIdx.x;
    int lane = threadIdx.x & 31, wid = threadIdx.x >> 5;
    int v = (i < N_NODES) ? g_hist[i] : 0;
    int inc = v;
#pragma unroll
    for (int off = 1; off < 32; off <<= 1) {
        int t = __shfl_up_sync(0xffffffffu, inc, off);
        if (lane >= off) inc += t;
    }
    if (lane == 31) wsum[wid] = inc;
    __syncthreads();
    if (wid == 0) {
        int s = wsum[lane];
#pragma unroll
        for (int off = 1; off < 32; off <<= 1) {
            int t = __shfl_up_sync(0xffffffffu, s, off);
            if (lane >= off) s += t;
        }
        wsum[lane] = s;
    }
    __syncthreads();
    int base = (wid > 0) ? wsum[wid - 1] : 0;
    if (i < N_NODES) g_offs[i] = base + inc - v;
    if (threadIdx.x == SCAN_BLK - 1) g_bsum[blockIdx.x] = base + inc;
}

__global__ void k_scan2() {   // single block, scan SCAN_NB (=98) block totals, exclusive
    __shared__ int wsum[4];
    int lane = threadIdx.x & 31, wid = threadIdx.x >> 5;
    int v = (threadIdx.x < SCAN_NB) ? g_bsum[threadIdx.x] : 0;
    int inc = v;
#pragma unroll
    for (int off = 1; off < 32; off <<= 1) {
        int t = __shfl_up_sync(0xffffffffu, inc, off);
        if (lane >= off) inc += t;
    }
    if (lane == 31) wsum[wid] = inc;
    __syncthreads();
    int base = 0;
    for (int w = 0; w < wid; w++) base += wsum[w];
    if (threadIdx.x < SCAN_NB) g_bsum[threadIdx.x] = base + inc - v;
}

__global__ void k_scan3() {   // apply block offsets; init cursor = offs
    int i = blockIdx.x * SCAN_BLK + threadIdx.x;
    if (i < N_NODES) {
        int o = g_offs[i] + g_bsum[blockIdx.x];
        g_offs[i]   = o;
        g_cursor[i] = o;
    }
}

// ---------------- fused: logits + leaky-relu + exp + denom + CSR scatter ----------------
// edge_attr/ei are one-shot streams -> __ldcs evict-first, preserving xl's L2 residency.
__global__ void k_logits(const float* __restrict__ edge_attr, const int* __restrict__ ei) {
    __shared__ float we_s[HC];
    if (threadIdx.x < HC) we_s[threadIdx.x] = g_we[threadIdx.x];
    __syncthreads();

    int e = blockIdx.x * blockDim.x + threadIdx.x;
    if (e >= N_EDGES) return;

    const float4* __restrict__ row = (const float4*)(edge_attr + (size_t)e * EDGE_CH);
    const float4* w0 = (const float4*)(we_s);
    const float4* w1 = (const float4*)(we_s + 32);
    const float4* w2 = (const float4*)(we_s + 64);
    const float4* w3 = (const float4*)(we_s + 96);
    float p0 = 0.f, p1 = 0.f, p2 = 0.f, p3 = 0.f;
#pragma unroll
    for (int i = 0; i < 8; i++) {
        float4 v = __ldcs(row + i);           // streaming: don't pollute L2
        float4 a0 = w0[i], a1 = w1[i], a2 = w2[i], a3 = w3[i];
        p0 += v.x * a0.x + v.y * a0.y + v.z * a0.z + v.w * a0.w;
        p1 += v.x * a1.x + v.y * a1.y + v.z * a1.z + v.w * a1.w;
        p2 += v.x * a2.x + v.y * a2.y + v.z * a2.z + v.w * a2.w;
        p3 += v.x * a3.x + v.y * a3.y + v.z * a3.z + v.w * a3.w;
    }
    int src = __ldcs(ei + e);
    int dst = __ldcs(ei + N_EDGES + e);
    float4 al = ((const float4*)g_al)[src];
    float4 ar = ((const float4*)g_ar)[dst];
    float a0 = al.x + ar.x + p0;
    float a1 = al.y + ar.y + p1;
    float a2 = al.z + ar.z + p2;
    float a3 = al.w + ar.w + p3;
    a0 = (a0 > 0.f) ? a0 : c_neg_slope * a0;
    a1 = (a1 > 0.f) ? a1 : c_neg_slope * a1;
    a2 = (a2 > 0.f) ? a2 : c_neg_slope * a2;
    a3 = (a3 > 0.f) ? a3 : c_neg_slope * a3;
    float4 ex = make_float4(__expf(a0), __expf(a1), __expf(a2), __expf(a3));
    int pos = atomicAdd(&g_cursor[dst], 1);
    g_csr_src[pos] = src;
    g_csr_ex[pos]  = ex;
    red_add_v4(&g_denom[dst], ex);
}

// ---------------- gather aggregation: one warp per dst node ----------------
// out is write-once -> __stcs so the 51MB output stream doesn't displace xl mid-kernel.
__global__ void k_agg(const float* __restrict__ bias, float* __restrict__ out) {
    const int lane = threadIdx.x & 31;
    const int h    = lane >> 3;                 // head owning this lane's float4
    int node = blockIdx.x * (blockDim.x >> 5) + (threadIdx.x >> 5);
    if (node >= N_NODES) return;

    int beg = g_offs[node];
    int end = g_cursor[node];                   // start + degree
    float4 acc = make_float4(0.f, 0.f, 0.f, 0.f);

    int pos = beg;
    for (; pos + 3 < end; pos += 4) {
        int s0 = g_csr_src[pos];
        int s1 = g_csr_src[pos + 1];
        int s2 = g_csr_src[pos + 2];
        int s3 = g_csr_src[pos + 3];
        float a0 = ((const float*)g_csr_ex)[(size_t)pos * 4 + h];
        float a1 = ((const float*)g_csr_ex)[(size_t)(pos + 1) * 4 + h];
        float a2 = ((const float*)g_csr_ex)[(size_t)(pos + 2) * 4 + h];
        float a3 = ((const float*)g_csr_ex)[(size_t)(pos + 3) * 4 + h];
        float4 v0 = ((const float4*)g_xl)[(size_t)s0 * 32 + lane];
        float4 v1 = ((const float4*)g_xl)[(size_t)s1 * 32 + lane];
        float4 v2 = ((const float4*)g_xl)[(size_t)s2 * 32 + lane];
        float4 v3 = ((const float4*)g_xl)[(size_t)s3 * 32 + lane];
        acc.x += a0 * v0.x + a1 * v1.x + a2 * v2.x + a3 * v3.x;
        acc.y += a0 * v0.y + a1 * v1.y + a2 * v2.y + a3 * v3.y;
        acc.z += a0 * v0.z + a1 * v1.z + a2 * v2.z + a3 * v3.z;
        acc.w += a0 * v0.w + a1 * v1.w + a2 * v2.w + a3 * v3.w;
    }
    for (; pos < end; pos++) {
        int s0 = g_csr_src[pos];
        float a0 = ((const float*)g_csr_ex)[(size_t)pos * 4 + h];
        float4 v0 = ((const float4*)g_xl)[(size_t)s0 * 32 + lane];
        acc.x += a0 * v0.x; acc.y += a0 * v0.y; acc.z += a0 * v0.z; acc.w += a0 * v0.w;
    }
    float inv = 1.0f / (((const float*)g_denom)[(size_t)node * 4 + h] + 1e-16f);
    float4 b = ((const float4*)bias)[lane];
    acc.x = acc.x * inv + b.x;
    acc.y = acc.y * inv + b.y;
    acc.z = acc.z * inv + b.z;
    acc.w = acc.w * inv + b.w;
    __stcs((float4*)out + (size_t)node * 32 + lane, acc);
}

// ---------------- launch: R9 schedule (gemm || edge-prep chain), cache-hinted kernels ----------------
extern "C" void kernel_launch(void* const* d_in, const int* in_sizes, int n_in,
                              void* d_out, int out_size) {
    const float* x         = (const float*)d_in[0];
    const float* edge_attr = (const float*)d_in[1];
    const float* Wl        = (const float*)d_in[2];
    const float* We        = (const float*)d_in[3];
    const float* att_l     = (const float*)d_in[4];
    const float* att_r     = (const float*)d_in[5];
    const float* att_e     = (const float*)d_in[6];
    const float* bias      = (const float*)d_in[7];
    const int*   ei        = (const int*)d_in[8];
    float* out = (float*)d_out;

    cudaStream_t sA, sB;
    cudaStreamCreateWithFlags(&sA, cudaStreamNonBlocking);
    cudaStreamCreateWithFlags(&sB, cudaStreamNonBlocking);
    cudaEvent_t evRoot, evA, evB;
    cudaEventCreateWithFlags(&evRoot, cudaEventDisableTiming);
    cudaEventCreateWithFlags(&evA,    cudaEventDisableTiming);
    cudaEventCreateWithFlags(&evB,    cudaEventDisableTiming);

    cudaEventRecord(evRoot, 0);
    cudaStreamWaitEvent(sA, evRoot, 0);
    cudaStreamWaitEvent(sB, evRoot, 0);

    // Branch A (sA): edge-prep chain — zero, hist, scans
    k_zero <<<(N_NODES * HEADS + 255) / 256, 256, 0, sA>>>();
    k_hist <<<(N_EDGES / 4 + 255) / 256, 256, 0, sA>>>(ei);
    k_scan1<<<SCAN_NB, SCAN_BLK, 0, sA>>>();
    k_scan2<<<1, 128, 0, sA>>>();
    k_scan3<<<SCAN_NB, SCAN_BLK, 0, sA>>>();
    cudaEventRecord(evA, sA);

    // Branch B (sB): tiny weight fold
    k_wepre<<<1, 128, 0, sB>>>(We, att_e);
    cudaEventRecord(evB, sB);

    // Main stream: FMA-bound GEMM overlaps branch A's L2/atomic work
    k_gemm<<<2368, 128>>>(x, Wl, att_l, att_r);

    // join
    cudaStreamWaitEvent(0, evA, 0);
    cudaStreamWaitEvent(0, evB, 0);

    k_logits<<<(N_EDGES + 255) / 256, 256>>>(edge_attr, ei);
    k_agg<<<(N_NODES * 32 + 255) / 256, 256>>>(bias, out);

    cudaEventDestroy(evRoot);
    cudaEventDestroy(evA);
    cudaEventDestroy(evB);
    cudaStreamDestroy(sA);
    cudaStreamDestroy(sB);
}